// round 3
// baseline (speedup 1.0000x reference)
#include <cuda_runtime.h>
#include <math.h>

// Problem constants
#define B_  8192
#define T_  128
#define D_  7
#define I_  128
#define C_  10
#define L_  128
#define TD_ 896   // T_*D_
#define LPPAD 12  // leafP row padded 10 -> 12 floats for aligned float4 loads

// ---------------- scratch (__device__ globals; no allocation) ----------------
__device__ float g_LP[T_ * L_ * LPPAD];          // softmaxed leaf probs, padded
__device__ float g_attn[B_ * T_];                // attention weights
__device__ float g_s[(size_t)B_ * TD_];          // softsign(z) [b][t*7+d], 29MB

// ---------------- kernel 1: leaf softmax (+ pad) ----------------
__global__ __launch_bounds__(256)
void prep_leaf_kernel(const float* __restrict__ leaf, float* __restrict__ lp) {
    int idx = blockIdx.x * blockDim.x + threadIdx.x;   // (t*128 + l), 16384 total
    if (idx >= T_ * L_) return;
    const float* in = leaf + (size_t)idx * C_;
    float v[C_];
    float m = -1e30f;
    #pragma unroll
    for (int c = 0; c < C_; c++) { v[c] = in[c]; m = fmaxf(m, v[c]); }
    float sum = 0.f;
    #pragma unroll
    for (int c = 0; c < C_; c++) { v[c] = expf(v[c] - m); sum += v[c]; }
    float inv = 1.0f / sum;
    float* o = lp + (size_t)idx * LPPAD;
    #pragma unroll
    for (int c = 0; c < C_; c++) o[c] = v[c] * inv;
    o[10] = 0.f; o[11] = 0.f;
}

// ---------------- kernel 2: MLP attention (warp per row b) ----------------
__global__ __launch_bounds__(256)
void attn_kernel(const float* __restrict__ x,  const float* __restrict__ W1,
                 const float* __restrict__ b1, const float* __restrict__ W2,
                 const float* __restrict__ b2, float* __restrict__ attn_out) {
    __shared__ float sx[8][128];
    __shared__ float sh[8][64];
    int w = threadIdx.x >> 5, lane = threadIdx.x & 31;
    int b = blockIdx.x * 8 + w;

    #pragma unroll
    for (int k = 0; k < 4; k++) sx[w][lane + 32 * k] = x[(size_t)b * I_ + lane + 32 * k];
    __syncwarp();

    float h0 = b1[lane], h1 = b1[lane + 32];
    #pragma unroll 4
    for (int i = 0; i < I_; i++) {
        float xi = sx[w][i];
        h0 = fmaf(xi, W1[i * 64 + lane],      h0);
        h1 = fmaf(xi, W1[i * 64 + lane + 32], h1);
    }
    sh[w][lane]      = fmaxf(h0, 0.f);
    sh[w][lane + 32] = fmaxf(h1, 0.f);
    __syncwarp();

    float lg[4];
    #pragma unroll
    for (int k = 0; k < 4; k++) lg[k] = b2[lane + 32 * k];
    #pragma unroll 4
    for (int j = 0; j < 64; j++) {
        float hj = sh[w][j];
        #pragma unroll
        for (int k = 0; k < 4; k++)
            lg[k] = fmaf(hj, W2[j * T_ + lane + 32 * k], lg[k]);
    }
    float m = fmaxf(fmaxf(lg[0], lg[1]), fmaxf(lg[2], lg[3]));
    #pragma unroll
    for (int o = 16; o; o >>= 1) m = fmaxf(m, __shfl_xor_sync(0xffffffffu, m, o));
    float sum = 0.f;
    #pragma unroll
    for (int k = 0; k < 4; k++) { lg[k] = expf(lg[k] - m); sum += lg[k]; }
    #pragma unroll
    for (int o = 16; o; o >>= 1) sum += __shfl_xor_sync(0xffffffffu, sum, o);
    float inv = 1.0f / sum;
    #pragma unroll
    for (int k = 0; k < 4; k++) attn_out[(size_t)b * T_ + lane + 32 * k] = lg[k] * inv;
}

// ---------------- kernel 3: z GEMM + softsign epilogue ----------------
// tile: 32 b-rows x 128 n-cols, K=128 fully resident in smem, 4x4 micro
#define KZ_SMEM_FLOATS (128 * 33 + 128 * 132)
__global__ __launch_bounds__(256)
void kz_kernel(const float* __restrict__ x, const float* __restrict__ fm,
               const float* __restrict__ thr, float* __restrict__ s_out) {
    extern __shared__ float smz[];
    float* As = smz;               // [k=128][m=32] pad 33
    float* Bs = smz + 128 * 33;    // [k=128][n=128] pad 132 (float4-aligned rows)
    int tid = threadIdx.x;
    int b0 = blockIdx.x * 32;
    int n0 = blockIdx.y * 128;

    for (int idx = tid; idx < 32 * 128; idx += 256) {
        int m = idx >> 7, k = idx & 127;
        As[k * 33 + m] = x[(size_t)(b0 + m) * I_ + k];
    }
    for (int idx = tid; idx < 128 * 128; idx += 256) {
        int n = idx >> 7, k = idx & 127;
        Bs[k * 132 + n] = fm[(size_t)(n0 + n) * I_ + k];
    }
    __syncthreads();

    int tn = tid & 31, tb = tid >> 5;          // warp: tb uniform -> A broadcast
    float acc[4][4] = {};
    const float4* Bs4 = (const float4*)Bs;     // row stride 33 float4s
    #pragma unroll 8
    for (int k = 0; k < 128; k++) {
        float a0 = As[k * 33 + tb * 4 + 0];
        float a1 = As[k * 33 + tb * 4 + 1];
        float a2 = As[k * 33 + tb * 4 + 2];
        float a3 = As[k * 33 + tb * 4 + 3];
        float4 bv = Bs4[k * 33 + tn];          // contiguous across lanes
        acc[0][0] = fmaf(a0, bv.x, acc[0][0]); acc[0][1] = fmaf(a0, bv.y, acc[0][1]);
        acc[0][2] = fmaf(a0, bv.z, acc[0][2]); acc[0][3] = fmaf(a0, bv.w, acc[0][3]);
        acc[1][0] = fmaf(a1, bv.x, acc[1][0]); acc[1][1] = fmaf(a1, bv.y, acc[1][1]);
        acc[1][2] = fmaf(a1, bv.z, acc[1][2]); acc[1][3] = fmaf(a1, bv.w, acc[1][3]);
        acc[2][0] = fmaf(a2, bv.x, acc[2][0]); acc[2][1] = fmaf(a2, bv.y, acc[2][1]);
        acc[2][2] = fmaf(a2, bv.z, acc[2][2]); acc[2][3] = fmaf(a2, bv.w, acc[2][3]);
        acc[3][0] = fmaf(a3, bv.x, acc[3][0]); acc[3][1] = fmaf(a3, bv.y, acc[3][1]);
        acc[3][2] = fmaf(a3, bv.z, acc[3][2]); acc[3][3] = fmaf(a3, bv.w, acc[3][3]);
    }

    int nBase = n0 + tn * 4;
    float t0 = thr[nBase + 0], t1 = thr[nBase + 1], t2 = thr[nBase + 2], t3 = thr[nBase + 3];
    #pragma unroll
    for (int u = 0; u < 4; u++) {
        int b = b0 + tb * 4 + u;
        float z0 = acc[u][0] - t0, z1 = acc[u][1] - t1;
        float z2 = acc[u][2] - t2, z3 = acc[u][3] - t3;
        float4 o;
        o.x = 0.5f * (z0 / (1.0f + fabsf(z0))) + 0.5f;
        o.y = 0.5f * (z1 / (1.0f + fabsf(z1))) + 0.5f;
        o.z = 0.5f * (z2 / (1.0f + fabsf(z2))) + 0.5f;
        o.w = 0.5f * (z3 / (1.0f + fabsf(z3))) + 0.5f;
        *(float4*)&s_out[(size_t)b * TD_ + nBase] = o;
    }
}

// ---------------- kernel 4: leaf products + mix + tree reduction ----------------
// block: 256 thr = 8 warps; warp w handles trees [w*16, w*16+16), lane = b within 32-row tile
#define TCH 16
#define KMIX_SMEM_FLOATS (8 * 1536 + 8 * 32 * 10)
__global__ __launch_bounds__(256)
void kmix_kernel(const float* __restrict__ s_in, const float* __restrict__ attn,
                 const float* __restrict__ lp, float* __restrict__ out) {
    extern __shared__ float smm[];
    float* sLP  = smm;                 // [8][128*12]
    float* sred = smm + 8 * 1536;      // [8][32][10]
    int w = threadIdx.x >> 5, lane = threadIdx.x & 31;
    int b = blockIdx.x * 32 + lane;

    float acc[C_];
    #pragma unroll
    for (int c = 0; c < C_; c++) acc[c] = 0.f;

    float* myLP = sLP + w * 1536;
    const float4* lp4 = (const float4*)lp;

    for (int tt = 0; tt < TCH; tt++) {
        int t = w * TCH + tt;
        __syncwarp();
        #pragma unroll
        for (int k = 0; k < 12; k++)
            ((float4*)myLP)[lane + 32 * k] = lp4[(size_t)t * 384 + lane + 32 * k];
        __syncwarp();

        float sv[D_], mv[D_];
        const float* sp = s_in + (size_t)b * TD_ + t * D_;
        #pragma unroll
        for (int d = 0; d < D_; d++) { sv[d] = sp[d]; mv[d] = 1.0f - sv[d]; }
        float a = attn[(size_t)b * T_ + t];

        // pLow over bits 0..2 (bit set -> (1-s))
        float pl[8];
        pl[0] = sv[0]; pl[1] = mv[0];
        pl[2] = pl[0] * mv[1]; pl[3] = pl[1] * mv[1];
        pl[0] *= sv[1];        pl[1] *= sv[1];
        pl[4] = pl[0] * mv[2]; pl[5] = pl[1] * mv[2];
        pl[6] = pl[2] * mv[2]; pl[7] = pl[3] * mv[2];
        pl[0] *= sv[2]; pl[1] *= sv[2]; pl[2] *= sv[2]; pl[3] *= sv[2];
        // pHigh over bits 3..6, attention folded in at level 0 (free)
        float ph[16];
        ph[0] = a * sv[3]; ph[1] = a * mv[3];
        ph[2] = ph[0] * mv[4]; ph[3] = ph[1] * mv[4];
        ph[0] *= sv[4];        ph[1] *= sv[4];
        ph[4] = ph[0] * mv[5]; ph[5] = ph[1] * mv[5];
        ph[6] = ph[2] * mv[5]; ph[7] = ph[3] * mv[5];
        ph[0] *= sv[5]; ph[1] *= sv[5]; ph[2] *= sv[5]; ph[3] *= sv[5];
        #pragma unroll
        for (int j = 0; j < 8; j++) ph[8 + j] = ph[j] * mv[6];
        #pragma unroll
        for (int j = 0; j < 8; j++) ph[j] *= sv[6];

        // mix: q_l = pl[l&7]*ph[l>>3]; acc_c += q_l * LP[t][l][c]
        #pragma unroll
        for (int m = 0; m < 16; m++) {
            float phm = ph[m];
            #pragma unroll
            for (int j = 0; j < 8; j++) {
                int l = m * 8 + j;
                float q = pl[j] * phm;
                const float* Lrow = myLP + l * LPPAD;
                float4 L0 = *(const float4*)(Lrow);       // broadcast LDS.128
                float4 L1 = *(const float4*)(Lrow + 4);
                float2 L2 = *(const float2*)(Lrow + 8);
                acc[0] = fmaf(q, L0.x, acc[0]); acc[1] = fmaf(q, L0.y, acc[1]);
                acc[2] = fmaf(q, L0.z, acc[2]); acc[3] = fmaf(q, L0.w, acc[3]);
                acc[4] = fmaf(q, L1.x, acc[4]); acc[5] = fmaf(q, L1.y, acc[5]);
                acc[6] = fmaf(q, L1.z, acc[6]); acc[7] = fmaf(q, L1.w, acc[7]);
                acc[8] = fmaf(q, L2.x, acc[8]); acc[9] = fmaf(q, L2.y, acc[9]);
            }
        }
    }

    // deterministic cross-warp (tree-chunk) reduction
    #pragma unroll
    for (int c = 0; c < C_; c++) sred[(w * 32 + lane) * C_ + c] = acc[c];
    __syncthreads();
    if (threadIdx.x < 32) {
        int bb = threadIdx.x;
        #pragma unroll
        for (int c = 0; c < C_; c++) {
            float v = 0.f;
            #pragma unroll
            for (int ww = 0; ww < 8; ww++) v += sred[(ww * 32 + bb) * C_ + c];
            out[(size_t)(blockIdx.x * 32 + bb) * C_ + c] = v;
        }
    }
}

// ---------------- launcher ----------------
extern "C" void kernel_launch(void* const* d_in, const int* in_sizes, int n_in,
                              void* d_out, int out_size) {
    const float* x    = (const float*)d_in[0];
    const float* fm   = (const float*)d_in[1];
    const float* thr  = (const float*)d_in[2];
    const float* leaf = (const float*)d_in[3];
    const float* W1   = (const float*)d_in[4];
    const float* b1   = (const float*)d_in[5];
    const float* W2   = (const float*)d_in[6];
    const float* b2   = (const float*)d_in[7];
    float* out = (float*)d_out;

    float* gLP;  cudaGetSymbolAddress((void**)&gLP,  g_LP);
    float* gAt;  cudaGetSymbolAddress((void**)&gAt,  g_attn);
    float* gS;   cudaGetSymbolAddress((void**)&gS,   g_s);

    static int attr_done = 0;
    // (idempotent attribute setup; not a device allocation, not stream-ordered)
    cudaFuncSetAttribute(kz_kernel,  cudaFuncAttributeMaxDynamicSharedMemorySize,
                         KZ_SMEM_FLOATS * 4);
    cudaFuncSetAttribute(kmix_kernel, cudaFuncAttributeMaxDynamicSharedMemorySize,
                         KMIX_SMEM_FLOATS * 4);
    (void)attr_done; (void)in_sizes; (void)n_in; (void)out_size;

    prep_leaf_kernel<<<(T_ * L_ + 255) / 256, 256>>>(leaf, gLP);
    attn_kernel<<<B_ / 8, 256>>>(x, W1, b1, W2, b2, gAt);
    kz_kernel<<<dim3(B_ / 32, TD_ / 128), 256, KZ_SMEM_FLOATS * 4>>>(x, fm, thr, gS);
    kmix_kernel<<<B_ / 32, 256, KMIX_SMEM_FLOATS * 4>>>(gS, gAt, gLP, out);
}